// round 3
// baseline (speedup 1.0000x reference)
#include <cuda_runtime.h>
#include <cuda_bf16.h>

// Problem constants (fixed by the dataset)
#define MAXN 100000
#define MAXE 1600000
#define HDIM 128
#define NSCAN_BLOCKS ((MAXN + 1023) / 1024)

// ---------------- scratch (device globals; no runtime allocation) ----------
__device__ float g_deg[MAXN];
__device__ int   g_cnt[MAXN];
__device__ int   g_rowptr[MAXN + 1];
__device__ int   g_fill[MAXN];
__device__ int   g_col[MAXE];
__device__ float g_nrm[MAXE];
__device__ int   g_bsum[NSCAN_BLOCKS + 1];
__device__ float g_h[(size_t)MAXN * HDIM];          // post-GEMM features (fp32)
__device__ __nv_bfloat16 g_hb[(size_t)MAXN * HDIM]; // bf16 copy of h (for gathers)
__device__ float g_x[(size_t)MAXN * HDIM];          // final-layer output (fp32, for pool)
__device__ __nv_bfloat16 g_xh[(size_t)MAXN * HDIM]; // GEMM input, hi bf16
__device__ __nv_bfloat16 g_xl[(size_t)MAXN * HDIM]; // GEMM input, lo bf16
__device__ __nv_bfloat16 g_Wh[3 * HDIM * HDIM];     // weights hi, TRANSPOSED [n][k]
__device__ __nv_bfloat16 g_Wl[3 * HDIM * HDIM];     // weights lo, TRANSPOSED [n][k]

// ---------------- CSR build -------------------------------------------------
__global__ void k_init(int n) {
    int i = blockIdx.x * blockDim.x + threadIdx.x;
    if (i < n) { g_cnt[i] = 0; g_fill[i] = 0; }
}

__global__ void k_count(const int* __restrict__ dst, int e) {
    int i = blockIdx.x * blockDim.x + threadIdx.x;
    if (i < e) atomicAdd(&g_cnt[dst[i]], 1);
}

__global__ void k_deg(int n) {
    int i = blockIdx.x * blockDim.x + threadIdx.x;
    if (i < n) g_deg[i] = (float)(g_cnt[i] + 1);
}

__global__ void k_scan1(int n) {
    int i = blockIdx.x * 1024 + threadIdx.x;
    int v = (i < n) ? g_cnt[i] : 0;
    int lane = threadIdx.x & 31, wid = threadIdx.x >> 5;
    int x = v;
    #pragma unroll
    for (int o = 1; o < 32; o <<= 1) {
        int y = __shfl_up_sync(0xFFFFFFFFu, x, o);
        if (lane >= o) x += y;
    }
    __shared__ int ws[32];
    if (lane == 31) ws[wid] = x;
    __syncthreads();
    if (wid == 0) {
        int w = ws[lane];
        #pragma unroll
        for (int o = 1; o < 32; o <<= 1) {
            int y = __shfl_up_sync(0xFFFFFFFFu, w, o);
            if (lane >= o) w += y;
        }
        ws[lane] = w;
    }
    __syncthreads();
    int prefix = (wid > 0) ? ws[wid - 1] : 0;
    int incl = x + prefix;
    if (i < n) g_rowptr[i] = incl - v;
    if (threadIdx.x == 1023) g_bsum[blockIdx.x] = incl;
}

__global__ void k_scan2(int nb) {
    if (threadIdx.x == 0 && blockIdx.x == 0) {
        int acc = 0;
        for (int b = 0; b < nb; b++) { int t = g_bsum[b]; g_bsum[b] = acc; acc += t; }
    }
}

__global__ void k_scan3(int n, int e) {
    int i = blockIdx.x * blockDim.x + threadIdx.x;
    if (i < n) g_rowptr[i] += g_bsum[i >> 10];
    if (i == 0) g_rowptr[n] = e;
}

__global__ void k_fill(const int* __restrict__ src, const int* __restrict__ dst, int e) {
    int i = blockIdx.x * blockDim.x + threadIdx.x;
    if (i >= e) return;
    int d = dst[i], s = src[i];
    int p = g_rowptr[d] + atomicAdd(&g_fill[d], 1);
    g_col[p] = s;
    g_nrm[p] = rsqrtf(g_deg[s] * g_deg[d]);
}

// ---------------- bf16 split helpers ----------------------------------------
__device__ __forceinline__ void split_bf16(float v, __nv_bfloat16& hi, __nv_bfloat16& lo) {
    hi = __float2bfloat16_rn(v);
    lo = __float2bfloat16_rn(v - __bfloat162float(hi));
}

// input fp32 x -> g_xh, g_xl (one float4 per thread)
__global__ void k_decomp(const float* __restrict__ in, int n) {
    int i = blockIdx.x * blockDim.x + threadIdx.x;   // i indexes float4
    if (i >= n * (HDIM / 4)) return;
    float4 v = ((const float4*)in)[i];
    __nv_bfloat16 h0, h1, h2, h3, l0, l1, l2, l3;
    split_bf16(v.x, h0, l0); split_bf16(v.y, h1, l1);
    split_bf16(v.z, h2, l2); split_bf16(v.w, h3, l3);
    __nv_bfloat16* ph = &g_xh[(size_t)i * 4];
    __nv_bfloat16* pl = &g_xl[(size_t)i * 4];
    ph[0] = h0; ph[1] = h1; ph[2] = h2; ph[3] = h3;
    pl[0] = l0; pl[1] = l1; pl[2] = l2; pl[3] = l3;
}

// weights: 3 x [k][n] fp32 -> transposed [n][k] bf16 hi/lo
__global__ void k_wconv(const float* __restrict__ W0, const float* __restrict__ W1,
                        const float* __restrict__ W2) {
    int i = blockIdx.x * blockDim.x + threadIdx.x;   // 3*128*128 threads
    if (i >= 3 * HDIM * HDIM) return;
    int l = i / (HDIM * HDIM);
    int r = i % (HDIM * HDIM);
    int nn = r / HDIM, kk = r % HDIM;
    const float* W = (l == 0) ? W0 : (l == 1) ? W1 : W2;
    float v = W[kk * HDIM + nn];
    __nv_bfloat16 hi, lo;
    split_bf16(v, hi, lo);
    g_Wh[l * HDIM * HDIM + nn * HDIM + kk] = hi;
    g_Wl[l * HDIM * HDIM + nn * HDIM + kk] = lo;
}

// ---------------- GEMM: H = X @ W + b via bf16 split mma.sync ---------------
// Tile 128x128, 256 threads (8 warps: 4 row-groups x 2 col-groups).
// 2-term split: D = Ah*Bh + Ah*Bl + Al*Bh, fp32 accumulate.
#define SKP 40   // padded smem row stride (32 + 8 bf16) for conflict-free LDS

__device__ __forceinline__ void mma_bf16(float* c, unsigned a0, unsigned a1,
                                         unsigned a2, unsigned a3,
                                         unsigned b0, unsigned b1) {
    asm volatile(
        "mma.sync.aligned.m16n8k16.row.col.f32.bf16.bf16.f32 "
        "{%0,%1,%2,%3}, {%4,%5,%6,%7}, {%8,%9}, {%0,%1,%2,%3};"
        : "+f"(c[0]), "+f"(c[1]), "+f"(c[2]), "+f"(c[3])
        : "r"(a0), "r"(a1), "r"(a2), "r"(a3), "r"(b0), "r"(b1));
}

__global__ __launch_bounds__(256) void k_gemm_mma(const __nv_bfloat16* __restrict__ Wh,
                                                  const __nv_bfloat16* __restrict__ Wl,
                                                  const float* __restrict__ bias,
                                                  int n) {
    __shared__ __nv_bfloat16 sAh[128][SKP];
    __shared__ __nv_bfloat16 sAl[128][SKP];
    __shared__ __nv_bfloat16 sBh[128][SKP];
    __shared__ __nv_bfloat16 sBl[128][SKP];

    int tid = threadIdx.x;
    int lane = tid & 31, wid = tid >> 5;
    int wr = wid & 3;        // row group (32 rows)
    int wc = wid >> 2;       // col group (64 cols)
    int blockRow = blockIdx.x * 128;
    int g = lane >> 2;       // group id 0..7
    int t = lane & 3;        // thread-in-group 0..3

    float c[2][8][4];
    #pragma unroll
    for (int mt = 0; mt < 2; mt++)
        #pragma unroll
        for (int nt = 0; nt < 8; nt++)
            #pragma unroll
            for (int j = 0; j < 4; j++) c[mt][nt][j] = 0.0f;

    for (int k0 = 0; k0 < HDIM; k0 += 32) {
        // load tiles: 128 rows x 32 cols bf16 = 512 x 16B per array, 2/thread
        #pragma unroll
        for (int i = 0; i < 2; i++) {
            int f = tid + i * 256;
            int r = f >> 2, c4 = (f & 3) << 3;   // 8 bf16 per uint4
            int row = blockRow + r;
            uint4 vh = make_uint4(0, 0, 0, 0), vl = make_uint4(0, 0, 0, 0);
            if (row < n) {
                vh = *(const uint4*)&g_xh[(size_t)row * HDIM + k0 + c4];
                vl = *(const uint4*)&g_xl[(size_t)row * HDIM + k0 + c4];
            }
            *(uint4*)&sAh[r][c4] = vh;
            *(uint4*)&sAl[r][c4] = vl;
            *(uint4*)&sBh[r][c4] = *(const uint4*)&Wh[(size_t)r * HDIM + k0 + c4];
            *(uint4*)&sBl[r][c4] = *(const uint4*)&Wl[(size_t)r * HDIM + k0 + c4];
        }
        __syncthreads();

        #pragma unroll
        for (int ks = 0; ks < 32; ks += 16) {
            unsigned ah[2][4], al[2][4];
            #pragma unroll
            for (int mt = 0; mt < 2; mt++) {
                int r0 = wr * 32 + mt * 16 + g;
                int cA = ks + 2 * t;
                ah[mt][0] = *(const unsigned*)&sAh[r0][cA];
                ah[mt][1] = *(const unsigned*)&sAh[r0 + 8][cA];
                ah[mt][2] = *(const unsigned*)&sAh[r0][cA + 8];
                ah[mt][3] = *(const unsigned*)&sAh[r0 + 8][cA + 8];
                al[mt][0] = *(const unsigned*)&sAl[r0][cA];
                al[mt][1] = *(const unsigned*)&sAl[r0 + 8][cA];
                al[mt][2] = *(const unsigned*)&sAl[r0][cA + 8];
                al[mt][3] = *(const unsigned*)&sAl[r0 + 8][cA + 8];
            }
            unsigned bh[8][2], bl[8][2];
            #pragma unroll
            for (int nt = 0; nt < 8; nt++) {
                int nn = wc * 64 + nt * 8 + g;
                int cB = ks + 2 * t;
                bh[nt][0] = *(const unsigned*)&sBh[nn][cB];
                bh[nt][1] = *(const unsigned*)&sBh[nn][cB + 8];
                bl[nt][0] = *(const unsigned*)&sBl[nn][cB];
                bl[nt][1] = *(const unsigned*)&sBl[nn][cB + 8];
            }
            #pragma unroll
            for (int mt = 0; mt < 2; mt++)
                #pragma unroll
                for (int nt = 0; nt < 8; nt++) {
                    mma_bf16(c[mt][nt], ah[mt][0], ah[mt][1], ah[mt][2], ah[mt][3],
                             bh[nt][0], bh[nt][1]);
                    mma_bf16(c[mt][nt], ah[mt][0], ah[mt][1], ah[mt][2], ah[mt][3],
                             bl[nt][0], bl[nt][1]);
                    mma_bf16(c[mt][nt], al[mt][0], al[mt][1], al[mt][2], al[mt][3],
                             bh[nt][0], bh[nt][1]);
                }
        }
        __syncthreads();
    }

    // epilogue: add bias, write fp32 g_h and bf16 g_hb
    #pragma unroll
    for (int nt = 0; nt < 8; nt++) {
        int col = wc * 64 + nt * 8 + 2 * t;
        float2 bv = *(const float2*)&bias[col];
        #pragma unroll
        for (int mt = 0; mt < 2; mt++) {
            int row0 = blockRow + wr * 32 + mt * 16 + g;
            float v0 = c[mt][nt][0] + bv.x;
            float v1 = c[mt][nt][1] + bv.y;
            float v2 = c[mt][nt][2] + bv.x;
            float v3 = c[mt][nt][3] + bv.y;
            if (row0 < n) {
                *(float2*)&g_h[(size_t)row0 * HDIM + col] = make_float2(v0, v1);
                __nv_bfloat162 p; p.x = __float2bfloat16_rn(v0); p.y = __float2bfloat16_rn(v1);
                *(__nv_bfloat162*)&g_hb[(size_t)row0 * HDIM + col] = p;
            }
            if (row0 + 8 < n) {
                *(float2*)&g_h[(size_t)(row0 + 8) * HDIM + col] = make_float2(v2, v3);
                __nv_bfloat162 p; p.x = __float2bfloat16_rn(v2); p.y = __float2bfloat16_rn(v3);
                *(__nv_bfloat162*)&g_hb[(size_t)(row0 + 8) * HDIM + col] = p;
            }
        }
    }
}

// ---------------- aggregation (bf16 gathers) --------------------------------
// x[i] = relu( h[i]/deg[i] + sum_{s in N(i)} hb[s]*nrm )
// mode 0: write split bf16 (g_xh/g_xl) for next GEMM; mode 1: write fp32 g_x.
__global__ __launch_bounds__(256) void k_aggregate(int n, int mode) {
    int node = (blockIdx.x * blockDim.x + threadIdx.x) >> 5;
    int lane = threadIdx.x & 31;
    if (node >= n) return;
    int cbase = lane * 4;  // 4 columns per lane

    float invd = 1.0f / g_deg[node];
    float4 acc = *(const float4*)&g_h[(size_t)node * HDIM + cbase];
    acc.x *= invd; acc.y *= invd; acc.z *= invd; acc.w *= invd;

    int beg = g_rowptr[node], end = g_rowptr[node + 1];
    int p = beg;
    for (; p + 1 < end; p += 2) {
        int s0 = g_col[p], s1 = g_col[p + 1];
        float w0 = g_nrm[p], w1 = g_nrm[p + 1];
        uint2 u0 = *(const uint2*)&g_hb[(size_t)s0 * HDIM + cbase];
        uint2 u1 = *(const uint2*)&g_hb[(size_t)s1 * HDIM + cbase];
        float2 a0 = __bfloat1622float2(*(__nv_bfloat162*)&u0.x);
        float2 b0 = __bfloat1622float2(*(__nv_bfloat162*)&u0.y);
        float2 a1 = __bfloat1622float2(*(__nv_bfloat162*)&u1.x);
        float2 b1 = __bfloat1622float2(*(__nv_bfloat162*)&u1.y);
        acc.x += a0.x * w0; acc.y += a0.y * w0; acc.z += b0.x * w0; acc.w += b0.y * w0;
        acc.x += a1.x * w1; acc.y += a1.y * w1; acc.z += b1.x * w1; acc.w += b1.y * w1;
    }
    if (p < end) {
        int s = g_col[p];
        float w = g_nrm[p];
        uint2 u = *(const uint2*)&g_hb[(size_t)s * HDIM + cbase];
        float2 a = __bfloat1622float2(*(__nv_bfloat162*)&u.x);
        float2 b = __bfloat1622float2(*(__nv_bfloat162*)&u.y);
        acc.x += a.x * w; acc.y += a.y * w; acc.z += b.x * w; acc.w += b.y * w;
    }
    acc.x = fmaxf(acc.x, 0.f); acc.y = fmaxf(acc.y, 0.f);
    acc.z = fmaxf(acc.z, 0.f); acc.w = fmaxf(acc.w, 0.f);

    if (mode == 1) {
        *(float4*)&g_x[(size_t)node * HDIM + cbase] = acc;
    } else {
        __nv_bfloat16 h0, h1, h2, h3, l0, l1, l2, l3;
        split_bf16(acc.x, h0, l0); split_bf16(acc.y, h1, l1);
        split_bf16(acc.z, h2, l2); split_bf16(acc.w, h3, l3);
        __nv_bfloat16* ph = &g_xh[(size_t)node * HDIM + cbase];
        __nv_bfloat16* pl = &g_xl[(size_t)node * HDIM + cbase];
        ph[0] = h0; ph[1] = h1; ph[2] = h2; ph[3] = h3;
        pl[0] = l0; pl[1] = l1; pl[2] = l2; pl[3] = l3;
    }
}

// ---------------- segment-mean pool + 2-layer MLP head ----------------------
__device__ __forceinline__ int lbound(const int* __restrict__ a, int n, int key) {
    int lo = 0, hi = n;
    while (lo < hi) { int m = (lo + hi) >> 1; if (a[m] < key) lo = m + 1; else hi = m; }
    return lo;
}

__global__ __launch_bounds__(128) void k_pool_mlp(const int* __restrict__ batch, int n,
                                                  const float* __restrict__ Wp1,
                                                  const float* __restrict__ bp1,
                                                  const float* __restrict__ Wp2,
                                                  const float* __restrict__ bp2,
                                                  float* __restrict__ out) {
    int g = blockIdx.x;
    int t = threadIdx.x;
    int beg = lbound(batch, n, g);
    int end = lbound(batch, n, g + 1);
    float s = 0.0f;
    for (int r = beg; r < end; r++) s += g_x[(size_t)r * HDIM + t];
    float cnt = (float)(end - beg);
    float inv = 1.0f / fmaxf(cnt, 1.0f);

    __shared__ float ps[HDIM];
    ps[t] = s * inv;
    __syncthreads();

    float hid = bp1[t];
    #pragma unroll
    for (int k = 0; k < HDIM; k++) hid += ps[k] * Wp1[k * HDIM + t];
    hid = fmaxf(hid, 0.0f);

    float term = hid * Wp2[t];
    #pragma unroll
    for (int o = 16; o > 0; o >>= 1) term += __shfl_down_sync(0xFFFFFFFFu, term, o);
    __shared__ float rs[4];
    int lane = t & 31, wid = t >> 5;
    if (lane == 0) rs[wid] = term;
    __syncthreads();
    if (t == 0) out[g] = rs[0] + rs[1] + rs[2] + rs[3] + bp2[0];
}

// ---------------- launch -----------------------------------------------------
extern "C" void kernel_launch(void* const* d_in, const int* in_sizes, int n_in,
                              void* d_out, int out_size) {
    const float* x     = (const float*)d_in[0];
    const int*   ei    = (const int*)d_in[1];
    const int*   batch = (const int*)d_in[2];
    const float* Ws[3] = {(const float*)d_in[3], (const float*)d_in[5], (const float*)d_in[7]};
    const float* bs[3] = {(const float*)d_in[4], (const float*)d_in[6], (const float*)d_in[8]};
    const float* Wp1 = (const float*)d_in[9];
    const float* bp1 = (const float*)d_in[10];
    const float* Wp2 = (const float*)d_in[11];
    const float* bp2 = (const float*)d_in[12];
    float* out = (float*)d_out;

    int n = in_sizes[0] / HDIM;
    int e = in_sizes[1] / 2;
    const int* src = ei;
    const int* dst = ei + e;

    int nb_n = (n + 255) / 256;
    int nb_e = (e + 255) / 256;
    int nscan = (n + 1023) / 1024;

    // CSR build
    k_init<<<nb_n, 256>>>(n);
    k_count<<<nb_e, 256>>>(dst, e);
    k_deg<<<nb_n, 256>>>(n);
    k_scan1<<<nscan, 1024>>>(n);
    k_scan2<<<1, 32>>>(nscan);
    k_scan3<<<nb_n, 256>>>(n, e);
    k_fill<<<nb_e, 256>>>(src, dst, e);

    // weight + input decomposition to bf16 hi/lo
    k_wconv<<<(3 * HDIM * HDIM + 255) / 256, 256>>>(Ws[0], Ws[1], Ws[2]);
    k_decomp<<<(n * (HDIM / 4) + 255) / 256, 256>>>(x, n);

    // 3 GCN layers
    int gemm_blocks = (n + 127) / 128;
    int agg_blocks = (n + 7) / 8;  // warp per node
    __nv_bfloat16* Wh0; cudaGetSymbolAddress((void**)&Wh0, g_Wh);
    __nv_bfloat16* Wl0; cudaGetSymbolAddress((void**)&Wl0, g_Wl);
    for (int l = 0; l < 3; l++) {
        k_gemm_mma<<<gemm_blocks, 256>>>(Wh0 + l * HDIM * HDIM, Wl0 + l * HDIM * HDIM,
                                         bs[l], n);
        k_aggregate<<<agg_blocks, 256>>>(n, (l == 2) ? 1 : 0);
    }

    // pool + MLP head
    k_pool_mlp<<<out_size, 128>>>(batch, n, Wp1, bp1, Wp2, bp2, out);
}

// round 4
// speedup vs baseline: 1.3526x; 1.3526x over previous
#include <cuda_runtime.h>
#include <cuda_bf16.h>

// Problem constants (fixed by the dataset)
#define MAXN 100000
#define MAXE 1600000
#define HDIM 128
#define NSCAN_BLOCKS ((MAXN + 1023) / 1024)

// ---------------- scratch (device globals; no runtime allocation) ----------
__device__ float g_deg[MAXN];          // degree incl. self-loop (float)
__device__ int   g_cnt[MAXN];          // in-degree histogram (int)
__device__ int   g_rowptr[MAXN + 1];   // CSR row pointers (by dst)
__device__ int   g_fill[MAXN];         // fill cursors
__device__ int   g_col[MAXE];          // CSR column (src node)
__device__ float g_nrm[MAXE];          // per-edge GCN norm
__device__ int   g_bsum[NSCAN_BLOCKS + 1];
__device__ float g_h[(size_t)MAXN * HDIM];          // post-GEMM features (fp32)
__device__ __nv_bfloat16 g_hb[(size_t)MAXN * HDIM]; // bf16 copy of h (gather stream)
__device__ float g_x[(size_t)MAXN * HDIM];          // post-aggregate features

// ---------------- CSR build -------------------------------------------------
__global__ void k_init(int n) {
    int i = blockIdx.x * blockDim.x + threadIdx.x;
    if (i < n) { g_cnt[i] = 0; g_fill[i] = 0; }
}

__global__ void k_count(const int* __restrict__ dst, int e) {
    int i = blockIdx.x * blockDim.x + threadIdx.x;
    if (i < e) atomicAdd(&g_cnt[dst[i]], 1);
}

__global__ void k_deg(int n) {
    int i = blockIdx.x * blockDim.x + threadIdx.x;
    if (i < n) g_deg[i] = (float)(g_cnt[i] + 1);
}

// block-level exclusive scan of g_cnt -> g_rowptr (partial), block sums -> g_bsum
__global__ void k_scan1(int n) {
    int i = blockIdx.x * 1024 + threadIdx.x;
    int v = (i < n) ? g_cnt[i] : 0;
    int lane = threadIdx.x & 31, wid = threadIdx.x >> 5;
    int x = v;
    #pragma unroll
    for (int o = 1; o < 32; o <<= 1) {
        int y = __shfl_up_sync(0xFFFFFFFFu, x, o);
        if (lane >= o) x += y;
    }
    __shared__ int ws[32];
    if (lane == 31) ws[wid] = x;
    __syncthreads();
    if (wid == 0) {
        int w = ws[lane];
        #pragma unroll
        for (int o = 1; o < 32; o <<= 1) {
            int y = __shfl_up_sync(0xFFFFFFFFu, w, o);
            if (lane >= o) w += y;
        }
        ws[lane] = w;
    }
    __syncthreads();
    int prefix = (wid > 0) ? ws[wid - 1] : 0;
    int incl = x + prefix;
    if (i < n) g_rowptr[i] = incl - v;  // exclusive within block
    if (threadIdx.x == 1023) g_bsum[blockIdx.x] = incl;
}

__global__ void k_scan2(int nb) {
    if (threadIdx.x == 0 && blockIdx.x == 0) {
        int acc = 0;
        for (int b = 0; b < nb; b++) { int t = g_bsum[b]; g_bsum[b] = acc; acc += t; }
    }
}

__global__ void k_scan3(int n, int e) {
    int i = blockIdx.x * blockDim.x + threadIdx.x;
    if (i < n) g_rowptr[i] += g_bsum[i >> 10];
    if (i == 0) g_rowptr[n] = e;
}

__global__ void k_fill(const int* __restrict__ src, const int* __restrict__ dst, int e) {
    int i = blockIdx.x * blockDim.x + threadIdx.x;
    if (i >= e) return;
    int d = dst[i], s = src[i];
    int p = g_rowptr[d] + atomicAdd(&g_fill[d], 1);
    g_col[p] = s;
    g_nrm[p] = rsqrtf(g_deg[s] * g_deg[d]);
}

// ---------------- GEMM: H = X @ W + b  (X: n x 128, W: 128 x 128) ----------
// R1 structure (pure fp32 FFMA, known-good) with a 4-kk inner step:
// A fetched as broadcast LDS.128 (4 k-values per row), B as LDS.128 per kk.
#define BM 64
#define BK 32
__global__ __launch_bounds__(256) void k_gemm(const float* __restrict__ Xin,
                                              int use_global,
                                              const float* __restrict__ W,
                                              const float* __restrict__ bias,
                                              int n) {
    const float* __restrict__ X = use_global ? g_x : Xin;
    __shared__ float As[BM][BK];    // 8 KB, row-major [m][k]
    __shared__ float Bs[BK][HDIM];  // 16 KB
    int tid = threadIdx.x;
    int tx = tid & 31;              // col group: cols tx*4 .. tx*4+3
    int ty = tid >> 5;              // row group: rows ty*8 .. ty*8+7
    int block_row = blockIdx.x * BM;
    float acc[8][4];
    #pragma unroll
    for (int r = 0; r < 8; r++)
        #pragma unroll
        for (int j = 0; j < 4; j++) acc[r][j] = 0.0f;

    for (int k0 = 0; k0 < HDIM; k0 += BK) {
        // load A tile: 64 x 32 floats = 512 float4, 2 per thread
        #pragma unroll
        for (int i = 0; i < 2; i++) {
            int f = tid + i * 256;
            int r = f >> 3, c = (f & 7) << 2;
            int row = block_row + r;
            float4 v = make_float4(0.f, 0.f, 0.f, 0.f);
            if (row < n) v = *(const float4*)&X[(size_t)row * HDIM + k0 + c];
            *(float4*)&As[r][c] = v;
        }
        // load B tile: 32 x 128 floats = 1024 float4, 4 per thread
        #pragma unroll
        for (int i = 0; i < 4; i++) {
            int f = tid + i * 256;
            int r = f >> 5, c = (f & 31) << 2;
            *(float4*)&Bs[r][c] = *(const float4*)&W[(size_t)(k0 + r) * HDIM + c];
        }
        __syncthreads();
        #pragma unroll
        for (int kk = 0; kk < BK; kk += 4) {
            // 4 B vectors (one per k)
            float4 b0 = *(float4*)&Bs[kk + 0][tx << 2];
            float4 b1 = *(float4*)&Bs[kk + 1][tx << 2];
            float4 b2 = *(float4*)&Bs[kk + 2][tx << 2];
            float4 b3 = *(float4*)&Bs[kk + 3][tx << 2];
            #pragma unroll
            for (int r = 0; r < 8; r++) {
                // one broadcast LDS.128: A[row][kk..kk+3]
                float4 a = *(float4*)&As[(ty << 3) + r][kk];
                acc[r][0] += a.x * b0.x; acc[r][1] += a.x * b0.y;
                acc[r][2] += a.x * b0.z; acc[r][3] += a.x * b0.w;
                acc[r][0] += a.y * b1.x; acc[r][1] += a.y * b1.y;
                acc[r][2] += a.y * b1.z; acc[r][3] += a.y * b1.w;
                acc[r][0] += a.z * b2.x; acc[r][1] += a.z * b2.y;
                acc[r][2] += a.z * b2.z; acc[r][3] += a.z * b2.w;
                acc[r][0] += a.w * b3.x; acc[r][1] += a.w * b3.y;
                acc[r][2] += a.w * b3.z; acc[r][3] += a.w * b3.w;
            }
        }
        __syncthreads();
    }
    float4 bv = *(const float4*)&bias[tx << 2];
    #pragma unroll
    for (int r = 0; r < 8; r++) {
        int row = block_row + (ty << 3) + r;
        if (row < n) {
            float4 o;
            o.x = acc[r][0] + bv.x;
            o.y = acc[r][1] + bv.y;
            o.z = acc[r][2] + bv.z;
            o.w = acc[r][3] + bv.w;
            *(float4*)&g_h[(size_t)row * HDIM + (tx << 2)] = o;
            // bf16 shadow copy for the gather-heavy aggregation
            __nv_bfloat162 p0, p1;
            p0.x = __float2bfloat16_rn(o.x); p0.y = __float2bfloat16_rn(o.y);
            p1.x = __float2bfloat16_rn(o.z); p1.y = __float2bfloat16_rn(o.w);
            uint2 pk;
            pk.x = *(unsigned*)&p0; pk.y = *(unsigned*)&p1;
            *(uint2*)&g_hb[(size_t)row * HDIM + (tx << 2)] = pk;
        }
    }
}

// ---------------- aggregation: x[i] = relu( h[i]/deg[i] + sum hb[src]*nrm ) -
// Gathers read the bf16 copy (half the L2 bytes); math stays fp32.
__global__ __launch_bounds__(256) void k_aggregate(int n) {
    int node = (blockIdx.x * blockDim.x + threadIdx.x) >> 5;
    int lane = threadIdx.x & 31;
    if (node >= n) return;
    int cbase = lane * 4;  // 4 feature columns per lane

    float invd = 1.0f / g_deg[node];
    float4 acc = *(const float4*)&g_h[(size_t)node * HDIM + cbase];
    acc.x *= invd; acc.y *= invd; acc.z *= invd; acc.w *= invd;

    int beg = g_rowptr[node], end = g_rowptr[node + 1];
    int p = beg;
    for (; p + 1 < end; p += 2) {
        int s0 = g_col[p], s1 = g_col[p + 1];
        float w0 = g_nrm[p], w1 = g_nrm[p + 1];
        uint2 u0 = *(const uint2*)&g_hb[(size_t)s0 * HDIM + cbase];
        uint2 u1 = *(const uint2*)&g_hb[(size_t)s1 * HDIM + cbase];
        float2 a0 = __bfloat1622float2(*(__nv_bfloat162*)&u0.x);
        float2 b0 = __bfloat1622float2(*(__nv_bfloat162*)&u0.y);
        float2 a1 = __bfloat1622float2(*(__nv_bfloat162*)&u1.x);
        float2 b1 = __bfloat1622float2(*(__nv_bfloat162*)&u1.y);
        acc.x += a0.x * w0; acc.y += a0.y * w0; acc.z += b0.x * w0; acc.w += b0.y * w0;
        acc.x += a1.x * w1; acc.y += a1.y * w1; acc.z += b1.x * w1; acc.w += b1.y * w1;
    }
    if (p < end) {
        int s = g_col[p];
        float w = g_nrm[p];
        uint2 u = *(const uint2*)&g_hb[(size_t)s * HDIM + cbase];
        float2 a = __bfloat1622float2(*(__nv_bfloat162*)&u.x);
        float2 b = __bfloat1622float2(*(__nv_bfloat162*)&u.y);
        acc.x += a.x * w; acc.y += a.y * w; acc.z += b.x * w; acc.w += b.y * w;
    }
    acc.x = fmaxf(acc.x, 0.f); acc.y = fmaxf(acc.y, 0.f);
    acc.z = fmaxf(acc.z, 0.f); acc.w = fmaxf(acc.w, 0.f);
    *(float4*)&g_x[(size_t)node * HDIM + cbase] = acc;
}

// ---------------- segment-mean pool + 2-layer MLP head ----------------------
__device__ __forceinline__ int lbound(const int* __restrict__ a, int n, int key) {
    int lo = 0, hi = n;
    while (lo < hi) { int m = (lo + hi) >> 1; if (a[m] < key) lo = m + 1; else hi = m; }
    return lo;
}

__global__ __launch_bounds__(128) void k_pool_mlp(const int* __restrict__ batch, int n,
                                                  const float* __restrict__ Wp1,
                                                  const float* __restrict__ bp1,
                                                  const float* __restrict__ Wp2,
                                                  const float* __restrict__ bp2,
                                                  float* __restrict__ out) {
    int g = blockIdx.x;
    int t = threadIdx.x;
    int beg = lbound(batch, n, g);
    int end = lbound(batch, n, g + 1);
    float s = 0.0f;
    for (int r = beg; r < end; r++) s += g_x[(size_t)r * HDIM + t];
    float cnt = (float)(end - beg);
    float inv = 1.0f / fmaxf(cnt, 1.0f);

    __shared__ float ps[HDIM];
    ps[t] = s * inv;
    __syncthreads();

    float hid = bp1[t];
    #pragma unroll
    for (int k = 0; k < HDIM; k++) hid += ps[k] * Wp1[k * HDIM + t];
    hid = fmaxf(hid, 0.0f);

    float term = hid * Wp2[t];
    #pragma unroll
    for (int o = 16; o > 0; o >>= 1) term += __shfl_down_sync(0xFFFFFFFFu, term, o);
    __shared__ float rs[4];
    int lane = t & 31, wid = t >> 5;
    if (lane == 0) rs[wid] = term;
    __syncthreads();
    if (t == 0) out[g] = rs[0] + rs[1] + rs[2] + rs[3] + bp2[0];
}

// ---------------- launch -----------------------------------------------------
extern "C" void kernel_launch(void* const* d_in, const int* in_sizes, int n_in,
                              void* d_out, int out_size) {
    const float* x     = (const float*)d_in[0];
    const int*   ei    = (const int*)d_in[1];
    const int*   batch = (const int*)d_in[2];
    const float* Ws[3] = {(const float*)d_in[3], (const float*)d_in[5], (const float*)d_in[7]};
    const float* bs[3] = {(const float*)d_in[4], (const float*)d_in[6], (const float*)d_in[8]};
    const float* Wp1 = (const float*)d_in[9];
    const float* bp1 = (const float*)d_in[10];
    const float* Wp2 = (const float*)d_in[11];
    const float* bp2 = (const float*)d_in[12];
    float* out = (float*)d_out;

    int n = in_sizes[0] / HDIM;
    int e = in_sizes[1] / 2;
    const int* src = ei;
    const int* dst = ei + e;

    int nb_n = (n + 255) / 256;
    int nb_e = (e + 255) / 256;
    int nscan = (n + 1023) / 1024;

    // CSR build
    k_init<<<nb_n, 256>>>(n);
    k_count<<<nb_e, 256>>>(dst, e);
    k_deg<<<nb_n, 256>>>(n);
    k_scan1<<<nscan, 1024>>>(n);
    k_scan2<<<1, 32>>>(nscan);
    k_scan3<<<nb_n, 256>>>(n, e);
    k_fill<<<nb_e, 256>>>(src, dst, e);

    // 3 GCN layers
    int gemm_blocks = (n + BM - 1) / BM;
    int agg_blocks = (n + 7) / 8;  // 8 warps per 256-thread block, warp per node
    for (int l = 0; l < 3; l++) {
        k_gemm<<<gemm_blocks, 256>>>(x, l > 0 ? 1 : 0, Ws[l], bs[l], n);
        k_aggregate<<<agg_blocks, 256>>>(n);
    }

    // pool + MLP head
    k_pool_mlp<<<out_size, 128>>>(batch, n, Wp1, bp1, Wp2, bp2, out);
}

// round 6
// speedup vs baseline: 2.0228x; 1.4955x over previous
#include <cuda_runtime.h>
#include <cuda_bf16.h>
#include <cstdint>

// Problem constants (fixed by the dataset)
#define MAXN 100000
#define MAXE 1600000
#define HDIM 128
#define NSCAN_BLOCKS ((MAXN + 1023) / 1024)

// ---------------- scratch (device globals; no runtime allocation) ----------
__device__ float g_deg[MAXN];
__device__ int   g_cnt[MAXN];
__device__ int   g_rowptr[MAXN + 1];
__device__ int   g_fill[MAXN];
__device__ int   g_col[MAXE];
__device__ float g_nrm[MAXE];
__device__ int   g_bsum[NSCAN_BLOCKS + 1];
__device__ __nv_bfloat16 g_hb[(size_t)MAXN * HDIM];  // post-GEMM features (bf16)
__device__ __nv_bfloat16 g_xb[(size_t)MAXN * HDIM];  // GEMM input (bf16)
__device__ float g_x[(size_t)MAXN * HDIM];           // final-layer fp32 (for pool)
__device__ __nv_bfloat16 g_Wth[3 * HDIM * HDIM];     // W^T hi  [n][k] bf16
__device__ __nv_bfloat16 g_Wtl[3 * HDIM * HDIM];     // W^T lo  [n][k] bf16

// ---------------- helpers ----------------------------------------------------
__device__ __forceinline__ uint32_t smem_to_u32(const void* p) {
    uint32_t a;
    asm("{ .reg .u64 t; cvta.to.shared.u64 t, %1; cvt.u32.u64 %0, t; }"
        : "=r"(a) : "l"(p));
    return a;
}

__device__ __forceinline__ void ldsm_x4(uint32_t addr, uint32_t& r0, uint32_t& r1,
                                        uint32_t& r2, uint32_t& r3) {
    asm volatile("ldmatrix.sync.aligned.m8n8.x4.shared.b16 {%0,%1,%2,%3}, [%4];"
                 : "=r"(r0), "=r"(r1), "=r"(r2), "=r"(r3) : "r"(addr));
}

__device__ __forceinline__ void mma_bf16(float* c, uint32_t a0, uint32_t a1,
                                         uint32_t a2, uint32_t a3,
                                         uint32_t b0, uint32_t b1) {
    asm volatile(
        "mma.sync.aligned.m16n8k16.row.col.f32.bf16.bf16.f32 "
        "{%0,%1,%2,%3}, {%4,%5,%6,%7}, {%8,%9}, {%0,%1,%2,%3};"
        : "+f"(c[0]), "+f"(c[1]), "+f"(c[2]), "+f"(c[3])
        : "r"(a0), "r"(a1), "r"(a2), "r"(a3), "r"(b0), "r"(b1));
}

__device__ __forceinline__ void split_bf16(float v, __nv_bfloat16& hi, __nv_bfloat16& lo) {
    hi = __float2bfloat16_rn(v);
    lo = __float2bfloat16_rn(v - __bfloat162float(hi));
}

// ---------------- CSR build -------------------------------------------------
__global__ void k_init(int n) {
    int i = blockIdx.x * blockDim.x + threadIdx.x;
    if (i < n) { g_cnt[i] = 0; g_fill[i] = 0; }
}

__global__ void k_count(const int* __restrict__ dst, int e) {
    int i = blockIdx.x * blockDim.x + threadIdx.x;
    if (i < e) atomicAdd(&g_cnt[dst[i]], 1);
}

__global__ void k_deg(int n) {
    int i = blockIdx.x * blockDim.x + threadIdx.x;
    if (i < n) g_deg[i] = (float)(g_cnt[i] + 1);
}

__global__ void k_scan1(int n) {
    int i = blockIdx.x * 1024 + threadIdx.x;
    int v = (i < n) ? g_cnt[i] : 0;
    int lane = threadIdx.x & 31, wid = threadIdx.x >> 5;
    int x = v;
    #pragma unroll
    for (int o = 1; o < 32; o <<= 1) {
        int y = __shfl_up_sync(0xFFFFFFFFu, x, o);
        if (lane >= o) x += y;
    }
    __shared__ int ws[32];
    if (lane == 31) ws[wid] = x;
    __syncthreads();
    if (wid == 0) {
        int w = ws[lane];
        #pragma unroll
        for (int o = 1; o < 32; o <<= 1) {
            int y = __shfl_up_sync(0xFFFFFFFFu, w, o);
            if (lane >= o) w += y;
        }
        ws[lane] = w;
    }
    __syncthreads();
    int prefix = (wid > 0) ? ws[wid - 1] : 0;
    int incl = x + prefix;
    if (i < n) g_rowptr[i] = incl - v;
    if (threadIdx.x == 1023) g_bsum[blockIdx.x] = incl;
}

__global__ void k_scan2(int nb) {
    if (threadIdx.x == 0 && blockIdx.x == 0) {
        int acc = 0;
        for (int b = 0; b < nb; b++) { int t = g_bsum[b]; g_bsum[b] = acc; acc += t; }
    }
}

__global__ void k_scan3(int n, int e) {
    int i = blockIdx.x * blockDim.x + threadIdx.x;
    if (i < n) g_rowptr[i] += g_bsum[i >> 10];
    if (i == 0) g_rowptr[n] = e;
}

__global__ void k_fill(const int* __restrict__ src, const int* __restrict__ dst, int e) {
    int i = blockIdx.x * blockDim.x + threadIdx.x;
    if (i >= e) return;
    int d = dst[i], s = src[i];
    int p = g_rowptr[d] + atomicAdd(&g_fill[d], 1);
    g_col[p] = s;
    g_nrm[p] = rsqrtf(g_deg[s] * g_deg[d]);
}

// ---------------- prep: weights transposed + split, input -> bf16 -----------
__global__ void k_wconv(const float* __restrict__ W0, const float* __restrict__ W1,
                        const float* __restrict__ W2) {
    int i = blockIdx.x * blockDim.x + threadIdx.x;
    if (i >= 3 * HDIM * HDIM) return;
    int l = i / (HDIM * HDIM);
    int r = i % (HDIM * HDIM);
    int nn = r / HDIM, kk = r % HDIM;
    const float* W = (l == 0) ? W0 : (l == 1) ? W1 : W2;
    float v = W[kk * HDIM + nn];
    __nv_bfloat16 hi, lo;
    split_bf16(v, hi, lo);
    g_Wth[l * HDIM * HDIM + nn * HDIM + kk] = hi;
    g_Wtl[l * HDIM * HDIM + nn * HDIM + kk] = lo;
}

__global__ void k_xb0(const float* __restrict__ x, int n) {
    int i = blockIdx.x * blockDim.x + threadIdx.x;  // 8 elements each
    if (i >= n * (HDIM / 8)) return;
    const float4* p = (const float4*)x + (size_t)i * 2;
    float4 v0 = p[0], v1 = p[1];
    __nv_bfloat162 a, b, c, d;
    a.x = __float2bfloat16_rn(v0.x); a.y = __float2bfloat16_rn(v0.y);
    b.x = __float2bfloat16_rn(v0.z); b.y = __float2bfloat16_rn(v0.w);
    c.x = __float2bfloat16_rn(v1.x); c.y = __float2bfloat16_rn(v1.y);
    d.x = __float2bfloat16_rn(v1.z); d.y = __float2bfloat16_rn(v1.w);
    uint4 o;
    o.x = *(uint32_t*)&a; o.y = *(uint32_t*)&b;
    o.z = *(uint32_t*)&c; o.w = *(uint32_t*)&d;
    *((uint4*)g_xb + i) = o;
}

// ---------------- GEMM: Hb = relu-less (Xb @ W + b) via mma.sync ------------
// 128x128 tile per CTA, 256 threads (8 warps = 4 row x 2 col groups).
// Whole K=128 in smem. 2 terms: A*Wh + A*Wl (W split; A single bf16).
#define PADB 272                       // 128*2 + 16 bytes per smem row
#define SM_A  0
#define SM_BH (128 * PADB)             // 34816
#define SM_BL (2 * 128 * PADB)         // 69632
#define SM_TOT (3 * 128 * PADB)        // 104448

__global__ __launch_bounds__(256, 2) void k_gemm_mma(
    const __nv_bfloat16* __restrict__ Wh,
    const __nv_bfloat16* __restrict__ Wl,
    const float* __restrict__ bias,
    int n)
{
    extern __shared__ __align__(16) char smem[];
    uint32_t sb = smem_to_u32(smem);
    int tid = threadIdx.x;
    int lane = tid & 31, wid = tid >> 5;
    int wr = wid & 3;          // row group: rows wr*32 .. +31
    int wc = wid >> 2;         // col group: cols wc*64 .. +63
    int blockRow = blockIdx.x * 128;

    // ---- fill smem: A (Xb rows), Bh, Bl. 2048 uint4 each, 8 per thread ----
    #pragma unroll
    for (int i = 0; i < 8; i++) {
        int gi = tid + i * 256;            // 0..2047
        int r = gi >> 4, c16 = gi & 15;    // row, 16B-chunk
        int row = blockRow + r;
        uint4 va = make_uint4(0, 0, 0, 0);
        if (row < n) va = *(const uint4*)&g_xb[(size_t)row * HDIM + c16 * 8];
        *(uint4*)(smem + SM_A + r * PADB + c16 * 16) = va;
        *(uint4*)(smem + SM_BH + r * PADB + c16 * 16) =
            *(const uint4*)&Wh[(size_t)r * HDIM + c16 * 8];
        *(uint4*)(smem + SM_BL + r * PADB + c16 * 16) =
            *(const uint4*)&Wl[(size_t)r * HDIM + c16 * 8];
    }
    __syncthreads();

    float c[2][8][4];
    #pragma unroll
    for (int mt = 0; mt < 2; mt++)
        #pragma unroll
        for (int nt = 0; nt < 8; nt++)
            #pragma unroll
            for (int j = 0; j < 4; j++) c[mt][nt][j] = 0.0f;

    int q = lane >> 3, rl = lane & 7;
    int rowA = wr * 32 + (q & 1) * 8 + rl;     // + mt*16
    int colA = (q >> 1) * 16;                  // + ks*32
    int rowB = wc * 64 + (q >> 1) * 8 + rl;    // + pr*16
    int colB = (q & 1) * 16;                   // + ks*32

    #pragma unroll
    for (int ks = 0; ks < 8; ks++) {
        uint32_t a[2][4];
        #pragma unroll
        for (int mt = 0; mt < 2; mt++)
            ldsm_x4(sb + SM_A + (rowA + mt * 16) * PADB + ks * 32 + colA,
                    a[mt][0], a[mt][1], a[mt][2], a[mt][3]);

        // pass 0: Wh, pass 1: Wl (reuse b regs)
        #pragma unroll
        for (int pass = 0; pass < 2; pass++) {
            uint32_t base = pass ? SM_BL : SM_BH;
            uint32_t b[8][2];
            #pragma unroll
            for (int pr = 0; pr < 4; pr++)
                ldsm_x4(sb + base + (rowB + pr * 16) * PADB + ks * 32 + colB,
                        b[2 * pr][0], b[2 * pr][1], b[2 * pr + 1][0], b[2 * pr + 1][1]);
            #pragma unroll
            for (int mt = 0; mt < 2; mt++)
                #pragma unroll
                for (int nt = 0; nt < 8; nt++)
                    mma_bf16(c[mt][nt], a[mt][0], a[mt][1], a[mt][2], a[mt][3],
                             b[nt][0], b[nt][1]);
        }
    }

    // ---- epilogue: bias + bf16 store ----
    int g = lane >> 2, t = lane & 3;
    #pragma unroll
    for (int nt = 0; nt < 8; nt++) {
        int col = wc * 64 + nt * 8 + 2 * t;
        float2 bv = *(const float2*)&bias[col];
        #pragma unroll
        for (int mt = 0; mt < 2; mt++) {
            int row0 = blockRow + wr * 32 + mt * 16 + g;
            if (row0 < n) {
                __nv_bfloat162 p;
                p.x = __float2bfloat16_rn(c[mt][nt][0] + bv.x);
                p.y = __float2bfloat16_rn(c[mt][nt][1] + bv.y);
                *(__nv_bfloat162*)&g_hb[(size_t)row0 * HDIM + col] = p;
            }
            if (row0 + 8 < n) {
                __nv_bfloat162 p;
                p.x = __float2bfloat16_rn(c[mt][nt][2] + bv.x);
                p.y = __float2bfloat16_rn(c[mt][nt][3] + bv.y);
                *(__nv_bfloat162*)&g_hb[(size_t)(row0 + 8) * HDIM + col] = p;
            }
        }
    }
}

// ---------------- aggregation: x[i] = relu( hb[i]/deg + sum hb[src]*nrm ) ---
// writes bf16 g_xb always; fp32 g_x on the last layer (for the pool).
__global__ __launch_bounds__(256) void k_aggregate(int n, int last) {
    int node = (blockIdx.x * blockDim.x + threadIdx.x) >> 5;
    int lane = threadIdx.x & 31;
    if (node >= n) return;
    int cbase = lane * 4;

    float invd = 1.0f / g_deg[node];
    uint2 us = *(const uint2*)&g_hb[(size_t)node * HDIM + cbase];
    float2 s0 = __bfloat1622float2(*(__nv_bfloat162*)&us.x);
    float2 s1 = __bfloat1622float2(*(__nv_bfloat162*)&us.y);
    float4 acc = make_float4(s0.x * invd, s0.y * invd, s1.x * invd, s1.y * invd);

    int beg = g_rowptr[node], end = g_rowptr[node + 1];
    int p = beg;
    for (; p + 1 < end; p += 2) {
        int sA = g_col[p], sB = g_col[p + 1];
        float w0 = g_nrm[p], w1 = g_nrm[p + 1];
        uint2 u0 = *(const uint2*)&g_hb[(size_t)sA * HDIM + cbase];
        uint2 u1 = *(const uint2*)&g_hb[(size_t)sB * HDIM + cbase];
        float2 a0 = __bfloat1622float2(*(__nv_bfloat162*)&u0.x);
        float2 b0 = __bfloat1622float2(*(__nv_bfloat162*)&u0.y);
        float2 a1 = __bfloat1622float2(*(__nv_bfloat162*)&u1.x);
        float2 b1 = __bfloat1622float2(*(__nv_bfloat162*)&u1.y);
        acc.x += a0.x * w0; acc.y += a0.y * w0; acc.z += b0.x * w0; acc.w += b0.y * w0;
        acc.x += a1.x * w1; acc.y += a1.y * w1; acc.z += b1.x * w1; acc.w += b1.y * w1;
    }
    if (p < end) {
        int s = g_col[p];
        float w = g_nrm[p];
        uint2 u = *(const uint2*)&g_hb[(size_t)s * HDIM + cbase];
        float2 a = __bfloat1622float2(*(__nv_bfloat162*)&u.x);
        float2 b = __bfloat1622float2(*(__nv_bfloat162*)&u.y);
        acc.x += a.x * w; acc.y += a.y * w; acc.z += b.x * w; acc.w += b.y * w;
    }
    acc.x = fmaxf(acc.x, 0.f); acc.y = fmaxf(acc.y, 0.f);
    acc.z = fmaxf(acc.z, 0.f); acc.w = fmaxf(acc.w, 0.f);

    __nv_bfloat162 p0, p1;
    p0.x = __float2bfloat16_rn(acc.x); p0.y = __float2bfloat16_rn(acc.y);
    p1.x = __float2bfloat16_rn(acc.z); p1.y = __float2bfloat16_rn(acc.w);
    uint2 pk; pk.x = *(uint32_t*)&p0; pk.y = *(uint32_t*)&p1;
    *(uint2*)&g_xb[(size_t)node * HDIM + cbase] = pk;
    if (last) *(float4*)&g_x[(size_t)node * HDIM + cbase] = acc;
}

// ---------------- segment-mean pool + 2-layer MLP head ----------------------
__device__ __forceinline__ int lbound(const int* __restrict__ a, int n, int key) {
    int lo = 0, hi = n;
    while (lo < hi) { int m = (lo + hi) >> 1; if (a[m] < key) lo = m + 1; else hi = m; }
    return lo;
}

__global__ __launch_bounds__(128) void k_pool_mlp(const int* __restrict__ batch, int n,
                                                  const float* __restrict__ Wp1,
                                                  const float* __restrict__ bp1,
                                                  const float* __restrict__ Wp2,
                                                  const float* __restrict__ bp2,
                                                  float* __restrict__ out) {
    int g = blockIdx.x;
    int t = threadIdx.x;
    int beg = lbound(batch, n, g);
    int end = lbound(batch, n, g + 1);
    float s = 0.0f;
    for (int r = beg; r < end; r++) s += g_x[(size_t)r * HDIM + t];
    float cnt = (float)(end - beg);
    float inv = 1.0f / fmaxf(cnt, 1.0f);

    __shared__ float ps[HDIM];
    ps[t] = s * inv;
    __syncthreads();

    float hid = bp1[t];
    #pragma unroll
    for (int k = 0; k < HDIM; k++) hid += ps[k] * Wp1[k * HDIM + t];
    hid = fmaxf(hid, 0.0f);

    float term = hid * Wp2[t];
    #pragma unroll
    for (int o = 16; o > 0; o >>= 1) term += __shfl_down_sync(0xFFFFFFFFu, term, o);
    __shared__ float rs[4];
    int lane = t & 31, wid = t >> 5;
    if (lane == 0) rs[wid] = term;
    __syncthreads();
    if (t == 0) out[g] = rs[0] + rs[1] + rs[2] + rs[3] + bp2[0];
}

// ---------------- launch -----------------------------------------------------
extern "C" void kernel_launch(void* const* d_in, const int* in_sizes, int n_in,
                              void* d_out, int out_size) {
    const float* x     = (const float*)d_in[0];
    const int*   ei    = (const int*)d_in[1];
    const int*   batch = (const int*)d_in[2];
    const float* Ws[3] = {(const float*)d_in[3], (const float*)d_in[5], (const float*)d_in[7]};
    const float* bs[3] = {(const float*)d_in[4], (const float*)d_in[6], (const float*)d_in[8]};
    const float* Wp1 = (const float*)d_in[9];
    const float* bp1 = (const float*)d_in[10];
    const float* Wp2 = (const float*)d_in[11];
    const float* bp2 = (const float*)d_in[12];
    float* out = (float*)d_out;

    int n = in_sizes[0] / HDIM;
    int e = in_sizes[1] / 2;
    const int* src = ei;
    const int* dst = ei + e;

    int nb_n = (n + 255) / 256;
    int nb_e = (e + 255) / 256;
    int nscan = (n + 1023) / 1024;

    // CSR build
    k_init<<<nb_n, 256>>>(n);
    k_count<<<nb_e, 256>>>(dst, e);
    k_deg<<<nb_n, 256>>>(n);
    k_scan1<<<nscan, 1024>>>(n);
    k_scan2<<<1, 32>>>(nscan);
    k_scan3<<<nb_n, 256>>>(n, e);
    k_fill<<<nb_e, 256>>>(src, dst, e);

    // prep: split-transposed weights, bf16 input
    k_wconv<<<(3 * HDIM * HDIM + 255) / 256, 256>>>(Ws[0], Ws[1], Ws[2]);
    k_xb0<<<(n * (HDIM / 8) + 255) / 256, 256>>>(x, n);

    cudaFuncSetAttribute(k_gemm_mma, cudaFuncAttributeMaxDynamicSharedMemorySize, SM_TOT);

    __nv_bfloat16* Wh0; cudaGetSymbolAddress((void**)&Wh0, g_Wth);
    __nv_bfloat16* Wl0; cudaGetSymbolAddress((void**)&Wl0, g_Wtl);

    // 3 GCN layers
    int gemm_blocks = (n + 127) / 128;
    int agg_blocks = (n + 7) / 8;
    for (int l = 0; l < 3; l++) {
        k_gemm_mma<<<gemm_blocks, 256, SM_TOT>>>(Wh0 + l * HDIM * HDIM,
                                                 Wl0 + l * HDIM * HDIM, bs[l], n);
        k_aggregate<<<agg_blocks, 256>>>(n, (l == 2) ? 1 : 0);
    }

    // pool + MLP head
    k_pool_mlp<<<out_size, 128>>>(batch, n, Wp1, bp1, Wp2, bp2, out);
}

// round 7
// speedup vs baseline: 2.2260x; 1.1004x over previous
#include <cuda_runtime.h>
#include <cuda_bf16.h>
#include <cstdint>

// Problem constants (fixed by the dataset)
#define MAXN 100000
#define MAXE 1600000
#define HDIM 128
#define NSCAN_BLOCKS ((MAXN + 1023) / 1024)

// ---------------- scratch (device globals; no runtime allocation) ----------
__device__ int   g_cnt[MAXN];
__device__ int   g_rowptr[MAXN + 1];
__device__ int   g_col[MAXE];
__device__ float g_nrm[MAXE];
__device__ int   g_bsum[NSCAN_BLOCKS + 1];
__device__ __nv_bfloat16 g_hb[(size_t)MAXN * HDIM];  // post-GEMM features (bf16)
__device__ __nv_bfloat16 g_xb[(size_t)MAXN * HDIM];  // GEMM input / pool input (bf16)
__device__ __nv_bfloat16 g_Wth[3 * HDIM * HDIM];     // W^T hi  [n][k] bf16
__device__ __nv_bfloat16 g_Wtl[3 * HDIM * HDIM];     // W^T lo  [n][k] bf16

// ---------------- helpers ----------------------------------------------------
__device__ __forceinline__ uint32_t smem_to_u32(const void* p) {
    uint32_t a;
    asm("{ .reg .u64 t; cvta.to.shared.u64 t, %1; cvt.u32.u64 %0, t; }"
        : "=r"(a) : "l"(p));
    return a;
}

__device__ __forceinline__ void ldsm_x4(uint32_t addr, uint32_t& r0, uint32_t& r1,
                                        uint32_t& r2, uint32_t& r3) {
    asm volatile("ldmatrix.sync.aligned.m8n8.x4.shared.b16 {%0,%1,%2,%3}, [%4];"
                 : "=r"(r0), "=r"(r1), "=r"(r2), "=r"(r3) : "r"(addr));
}

__device__ __forceinline__ void mma_bf16(float* c, uint32_t a0, uint32_t a1,
                                         uint32_t a2, uint32_t a3,
                                         uint32_t b0, uint32_t b1) {
    asm volatile(
        "mma.sync.aligned.m16n8k16.row.col.f32.bf16.bf16.f32 "
        "{%0,%1,%2,%3}, {%4,%5,%6,%7}, {%8,%9}, {%0,%1,%2,%3};"
        : "+f"(c[0]), "+f"(c[1]), "+f"(c[2]), "+f"(c[3])
        : "r"(a0), "r"(a1), "r"(a2), "r"(a3), "r"(b0), "r"(b1));
}

__device__ __forceinline__ void split_bf16(float v, __nv_bfloat16& hi, __nv_bfloat16& lo) {
    hi = __float2bfloat16_rn(v);
    lo = __float2bfloat16_rn(v - __bfloat162float(hi));
}

// ---------------- CSR build -------------------------------------------------
__global__ void k_init(int n) {
    int i = blockIdx.x * blockDim.x + threadIdx.x;
    if (i < n) g_cnt[i] = 0;
}

__global__ void k_count(const int* __restrict__ dst, int e) {
    int i = blockIdx.x * blockDim.x + threadIdx.x;
    if (i < e) atomicAdd(&g_cnt[dst[i]], 1);
}

__global__ void k_scan1(int n) {
    int i = blockIdx.x * 1024 + threadIdx.x;
    int v = (i < n) ? g_cnt[i] : 0;
    int lane = threadIdx.x & 31, wid = threadIdx.x >> 5;
    int x = v;
    #pragma unroll
    for (int o = 1; o < 32; o <<= 1) {
        int y = __shfl_up_sync(0xFFFFFFFFu, x, o);
        if (lane >= o) x += y;
    }
    __shared__ int ws[32];
    if (lane == 31) ws[wid] = x;
    __syncthreads();
    if (wid == 0) {
        int w = ws[lane];
        #pragma unroll
        for (int o = 1; o < 32; o <<= 1) {
            int y = __shfl_up_sync(0xFFFFFFFFu, w, o);
            if (lane >= o) w += y;
        }
        ws[lane] = w;
    }
    __syncthreads();
    int prefix = (wid > 0) ? ws[wid - 1] : 0;
    int incl = x + prefix;
    if (i < n) g_rowptr[i] = incl - v;
    if (threadIdx.x == 1023) g_bsum[blockIdx.x] = incl;
}

__global__ void k_scan2(int nb) {
    if (threadIdx.x == 0 && blockIdx.x == 0) {
        int acc = 0;
        for (int b = 0; b < nb; b++) { int t = g_bsum[b]; g_bsum[b] = acc; acc += t; }
    }
}

__global__ void k_scan3(int n, int e) {
    int i = blockIdx.x * blockDim.x + threadIdx.x;
    if (i < n) g_rowptr[i] += g_bsum[i >> 10];
    if (i == 0) g_rowptr[n] = e;
}

// countdown-cursor fill; degree recomputed from rowptr diffs (+1 self-loop)
__global__ void k_fill(const int* __restrict__ src, const int* __restrict__ dst, int e) {
    int i = blockIdx.x * blockDim.x + threadIdx.x;
    if (i >= e) return;
    int d = dst[i], s = src[i];
    int rpd1 = g_rowptr[d + 1];
    int c = atomicAdd(&g_cnt[d], -1);          // old value: cnt .. 1
    int p = rpd1 - c;                          // rowptr[d] .. rowptr[d+1]-1
    float degd = (float)(rpd1 - g_rowptr[d] + 1);
    float degs = (float)(g_rowptr[s + 1] - g_rowptr[s] + 1);
    g_col[p] = s;
    g_nrm[p] = rsqrtf(degs * degd);
}

// ---------------- prep: weights transposed + split, input -> bf16 -----------
__global__ void k_wconv(const float* __restrict__ W0, const float* __restrict__ W1,
                        const float* __restrict__ W2) {
    int i = blockIdx.x * blockDim.x + threadIdx.x;
    if (i >= 3 * HDIM * HDIM) return;
    int l = i / (HDIM * HDIM);
    int r = i % (HDIM * HDIM);
    int nn = r / HDIM, kk = r % HDIM;
    const float* W = (l == 0) ? W0 : (l == 1) ? W1 : W2;
    float v = W[kk * HDIM + nn];
    __nv_bfloat16 hi, lo;
    split_bf16(v, hi, lo);
    g_Wth[l * HDIM * HDIM + nn * HDIM + kk] = hi;
    g_Wtl[l * HDIM * HDIM + nn * HDIM + kk] = lo;
}

__global__ void k_xb0(const float* __restrict__ x, int n) {
    int i = blockIdx.x * blockDim.x + threadIdx.x;  // 8 elements each
    if (i >= n * (HDIM / 8)) return;
    const float4* p = (const float4*)x + (size_t)i * 2;
    float4 v0 = p[0], v1 = p[1];
    __nv_bfloat162 a, b, c, d;
    a.x = __float2bfloat16_rn(v0.x); a.y = __float2bfloat16_rn(v0.y);
    b.x = __float2bfloat16_rn(v0.z); b.y = __float2bfloat16_rn(v0.w);
    c.x = __float2bfloat16_rn(v1.x); c.y = __float2bfloat16_rn(v1.y);
    d.x = __float2bfloat16_rn(v1.z); d.y = __float2bfloat16_rn(v1.w);
    uint4 o;
    o.x = *(uint32_t*)&a; o.y = *(uint32_t*)&b;
    o.z = *(uint32_t*)&c; o.w = *(uint32_t*)&d;
    *((uint4*)g_xb + i) = o;
}

// ---------------- GEMM: Hb = Xb @ W + b via mma.sync (unchanged from R6) ----
#define PADB 272
#define SM_A  0
#define SM_BH (128 * PADB)
#define SM_BL (2 * 128 * PADB)
#define SM_TOT (3 * 128 * PADB)

__global__ __launch_bounds__(256, 2) void k_gemm_mma(
    const __nv_bfloat16* __restrict__ Wh,
    const __nv_bfloat16* __restrict__ Wl,
    const float* __restrict__ bias,
    int n)
{
    extern __shared__ __align__(16) char smem[];
    uint32_t sb = smem_to_u32(smem);
    int tid = threadIdx.x;
    int lane = tid & 31, wid = tid >> 5;
    int wr = wid & 3;
    int wc = wid >> 2;
    int blockRow = blockIdx.x * 128;

    #pragma unroll
    for (int i = 0; i < 8; i++) {
        int gi = tid + i * 256;
        int r = gi >> 4, c16 = gi & 15;
        int row = blockRow + r;
        uint4 va = make_uint4(0, 0, 0, 0);
        if (row < n) va = *(const uint4*)&g_xb[(size_t)row * HDIM + c16 * 8];
        *(uint4*)(smem + SM_A + r * PADB + c16 * 16) = va;
        *(uint4*)(smem + SM_BH + r * PADB + c16 * 16) =
            *(const uint4*)&Wh[(size_t)r * HDIM + c16 * 8];
        *(uint4*)(smem + SM_BL + r * PADB + c16 * 16) =
            *(const uint4*)&Wl[(size_t)r * HDIM + c16 * 8];
    }
    __syncthreads();

    float c[2][8][4];
    #pragma unroll
    for (int mt = 0; mt < 2; mt++)
        #pragma unroll
        for (int nt = 0; nt < 8; nt++)
            #pragma unroll
            for (int j = 0; j < 4; j++) c[mt][nt][j] = 0.0f;

    int q = lane >> 3, rl = lane & 7;
    int rowA = wr * 32 + (q & 1) * 8 + rl;
    int colA = (q >> 1) * 16;
    int rowB = wc * 64 + (q >> 1) * 8 + rl;
    int colB = (q & 1) * 16;

    #pragma unroll
    for (int ks = 0; ks < 8; ks++) {
        uint32_t a[2][4];
        #pragma unroll
        for (int mt = 0; mt < 2; mt++)
            ldsm_x4(sb + SM_A + (rowA + mt * 16) * PADB + ks * 32 + colA,
                    a[mt][0], a[mt][1], a[mt][2], a[mt][3]);

        #pragma unroll
        for (int pass = 0; pass < 2; pass++) {
            uint32_t base = pass ? SM_BL : SM_BH;
            uint32_t b[8][2];
            #pragma unroll
            for (int pr = 0; pr < 4; pr++)
                ldsm_x4(sb + base + (rowB + pr * 16) * PADB + ks * 32 + colB,
                        b[2 * pr][0], b[2 * pr][1], b[2 * pr + 1][0], b[2 * pr + 1][1]);
            #pragma unroll
            for (int mt = 0; mt < 2; mt++)
                #pragma unroll
                for (int nt = 0; nt < 8; nt++)
                    mma_bf16(c[mt][nt], a[mt][0], a[mt][1], a[mt][2], a[mt][3],
                             b[nt][0], b[nt][1]);
        }
    }

    int g = lane >> 2, t = lane & 3;
    #pragma unroll
    for (int nt = 0; nt < 8; nt++) {
        int col = wc * 64 + nt * 8 + 2 * t;
        float2 bv = *(const float2*)&bias[col];
        #pragma unroll
        for (int mt = 0; mt < 2; mt++) {
            int row0 = blockRow + wr * 32 + mt * 16 + g;
            if (row0 < n) {
                __nv_bfloat162 p;
                p.x = __float2bfloat16_rn(c[mt][nt][0] + bv.x);
                p.y = __float2bfloat16_rn(c[mt][nt][1] + bv.y);
                *(__nv_bfloat162*)&g_hb[(size_t)row0 * HDIM + col] = p;
            }
            if (row0 + 8 < n) {
                __nv_bfloat162 p;
                p.x = __float2bfloat16_rn(c[mt][nt][2] + bv.x);
                p.y = __float2bfloat16_rn(c[mt][nt][3] + bv.y);
                *(__nv_bfloat162*)&g_hb[(size_t)(row0 + 8) * HDIM + col] = p;
            }
        }
    }
}

// ---------------- aggregation: half-warp per node, uint4 per lane -----------
// xb[i] = relu( hb[i]/deg + sum_{s in N(i)} hb[s]*nrm )
__device__ __forceinline__ void acc8(float* a, uint4 u, float w) {
    float2 t;
    t = __bfloat1622float2(*(__nv_bfloat162*)&u.x); a[0] += t.x * w; a[1] += t.y * w;
    t = __bfloat1622float2(*(__nv_bfloat162*)&u.y); a[2] += t.x * w; a[3] += t.y * w;
    t = __bfloat1622float2(*(__nv_bfloat162*)&u.z); a[4] += t.x * w; a[5] += t.y * w;
    t = __bfloat1622float2(*(__nv_bfloat162*)&u.w); a[6] += t.x * w; a[7] += t.y * w;
}

__global__ __launch_bounds__(256) void k_aggregate(int n) {
    int node = (blockIdx.x * blockDim.x + threadIdx.x) >> 4;   // half-warp per node
    int hl = threadIdx.x & 15;
    if (node >= n) return;
    int cbase = hl * 8;   // 8 bf16 cols per lane (16 B)

    int beg = g_rowptr[node], end = g_rowptr[node + 1];
    float invd = 1.0f / (float)(end - beg + 1);

    float a[8];
    {
        uint4 us = *(const uint4*)&g_hb[(size_t)node * HDIM + cbase];
        float2 t;
        t = __bfloat1622float2(*(__nv_bfloat162*)&us.x); a[0] = t.x * invd; a[1] = t.y * invd;
        t = __bfloat1622float2(*(__nv_bfloat162*)&us.y); a[2] = t.x * invd; a[3] = t.y * invd;
        t = __bfloat1622float2(*(__nv_bfloat162*)&us.z); a[4] = t.x * invd; a[5] = t.y * invd;
        t = __bfloat1622float2(*(__nv_bfloat162*)&us.w); a[6] = t.x * invd; a[7] = t.y * invd;
    }

    int p = beg;
    for (; p + 1 < end; p += 2) {
        int s0 = g_col[p], s1 = g_col[p + 1];
        float w0 = g_nrm[p], w1 = g_nrm[p + 1];
        uint4 u0 = *(const uint4*)&g_hb[(size_t)s0 * HDIM + cbase];
        uint4 u1 = *(const uint4*)&g_hb[(size_t)s1 * HDIM + cbase];
        acc8(a, u0, w0);
        acc8(a, u1, w1);
    }
    if (p < end) {
        int s = g_col[p];
        float w = g_nrm[p];
        uint4 u = *(const uint4*)&g_hb[(size_t)s * HDIM + cbase];
        acc8(a, u, w);
    }

    #pragma unroll
    for (int j = 0; j < 8; j++) a[j] = fmaxf(a[j], 0.0f);

    __nv_bfloat162 p0, p1, p2, p3;
    p0.x = __float2bfloat16_rn(a[0]); p0.y = __float2bfloat16_rn(a[1]);
    p1.x = __float2bfloat16_rn(a[2]); p1.y = __float2bfloat16_rn(a[3]);
    p2.x = __float2bfloat16_rn(a[4]); p2.y = __float2bfloat16_rn(a[5]);
    p3.x = __float2bfloat16_rn(a[6]); p3.y = __float2bfloat16_rn(a[7]);
    uint4 pk;
    pk.x = *(uint32_t*)&p0; pk.y = *(uint32_t*)&p1;
    pk.z = *(uint32_t*)&p2; pk.w = *(uint32_t*)&p3;
    *(uint4*)&g_xb[(size_t)node * HDIM + cbase] = pk;
}

// ---------------- segment-mean pool (bf16 input) + 2-layer MLP head ---------
__device__ __forceinline__ int lbound(const int* __restrict__ a, int n, int key) {
    int lo = 0, hi = n;
    while (lo < hi) { int m = (lo + hi) >> 1; if (a[m] < key) lo = m + 1; else hi = m; }
    return lo;
}

__global__ __launch_bounds__(128) void k_pool_mlp(const int* __restrict__ batch, int n,
                                                  const float* __restrict__ Wp1,
                                                  const float* __restrict__ bp1,
                                                  const float* __restrict__ Wp2,
                                                  const float* __restrict__ bp2,
                                                  float* __restrict__ out) {
    int g = blockIdx.x;
    int t = threadIdx.x;
    int beg = lbound(batch, n, g);
    int end = lbound(batch, n, g + 1);
    float s = 0.0f;
    for (int r = beg; r < end; r++)
        s += __bfloat162float(g_xb[(size_t)r * HDIM + t]);
    float cnt = (float)(end - beg);
    float inv = 1.0f / fmaxf(cnt, 1.0f);

    __shared__ float ps[HDIM];
    ps[t] = s * inv;
    __syncthreads();

    float hid = bp1[t];
    #pragma unroll
    for (int k = 0; k < HDIM; k++) hid += ps[k] * Wp1[k * HDIM + t];
    hid = fmaxf(hid, 0.0f);

    float term = hid * Wp2[t];
    #pragma unroll
    for (int o = 16; o > 0; o >>= 1) term += __shfl_down_sync(0xFFFFFFFFu, term, o);
    __shared__ float rs[4];
    int lane = t & 31, wid = t >> 5;
    if (lane == 0) rs[wid] = term;
    __syncthreads();
    if (t == 0) out[g] = rs[0] + rs[1] + rs[2] + rs[3] + bp2[0];
}

// ---------------- launch -----------------------------------------------------
extern "C" void kernel_launch(void* const* d_in, const int* in_sizes, int n_in,
                              void* d_out, int out_size) {
    const float* x     = (const float*)d_in[0];
    const int*   ei    = (const int*)d_in[1];
    const int*   batch = (const int*)d_in[2];
    const float* Ws[3] = {(const float*)d_in[3], (const float*)d_in[5], (const float*)d_in[7]};
    const float* bs[3] = {(const float*)d_in[4], (const float*)d_in[6], (const float*)d_in[8]};
    const float* Wp1 = (const float*)d_in[9];
    const float* bp1 = (const float*)d_in[10];
    const float* Wp2 = (const float*)d_in[11];
    const float* bp2 = (const float*)d_in[12];
    float* out = (float*)d_out;

    int n = in_sizes[0] / HDIM;
    int e = in_sizes[1] / 2;
    const int* src = ei;
    const int* dst = ei + e;

    int nb_n = (n + 255) / 256;
    int nb_e = (e + 255) / 256;
    int nscan = (n + 1023) / 1024;

    // CSR build
    k_init<<<nb_n, 256>>>(n);
    k_count<<<nb_e, 256>>>(dst, e);
    k_scan1<<<nscan, 1024>>>(n);
    k_scan2<<<1, 32>>>(nscan);
    k_scan3<<<nb_n, 256>>>(n, e);
    k_fill<<<nb_e, 256>>>(src, dst, e);

    // prep: split-transposed weights, bf16 input
    k_wconv<<<(3 * HDIM * HDIM + 255) / 256, 256>>>(Ws[0], Ws[1], Ws[2]);
    k_xb0<<<(n * (HDIM / 8) + 255) / 256, 256>>>(x, n);

    cudaFuncSetAttribute(k_gemm_mma, cudaFuncAttributeMaxDynamicSharedMemorySize, SM_TOT);

    __nv_bfloat16* Wh0; cudaGetSymbolAddress((void**)&Wh0, g_Wth);
    __nv_bfloat16* Wl0; cudaGetSymbolAddress((void**)&Wl0, g_Wtl);

    // 3 GCN layers
    int gemm_blocks = (n + 127) / 128;
    int agg_blocks = (n + 15) / 16;  // 16 half-warps per 256-thread block
    for (int l = 0; l < 3; l++) {
        k_gemm_mma<<<gemm_blocks, 256, SM_TOT>>>(Wh0 + l * HDIM * HDIM,
                                                 Wl0 + l * HDIM * HDIM, bs[l], n);
        k_aggregate<<<agg_blocks, 256>>>(n);
    }

    // pool + MLP head
    k_pool_mlp<<<out_size, 128>>>(batch, n, Wp1, bp1, Wp2, bp2, out);
}